// round 15
// baseline (speedup 1.0000x reference)
#include <cuda_runtime.h>
#include <cstdint>
#include <cstddef>

#define BSZ   16384
#define H     512
#define KD    1152            // 128 + 2*512
#define NTOT  2560            // 5 gates * 512
#define NCH   72              // K chunks of 16
#define NTILES 16             // 2560 / 160
#define MTILES 64             // 16384 / 256
#define LDE   165             // epilogue staging stride (floats)
#define STAGE_F4 1664         // A 1024 f4 (256rows x 64B) + B 640 f4 per chunk
#define NSTG  4
#define SMEM_DYN (NSTG * STAGE_F4 * 16)   // 106496

// --------- device-global scratch (no allocation calls anywhere) ----------
static __device__ float g_Xp[(size_t)BSZ * KD];          // 75.5 MB fragment-ordered
static __device__ float g_Wp[(size_t)NTOT * KD];         // 11.8 MB fragment-ordered

// ------------------------------ helpers ---------------------------------
__device__ __forceinline__ float tfr(float f) {
    uint32_t u; asm("cvt.rna.tf32.f32 %0, %1;" : "=r"(u) : "f"(f));
    return __uint_as_float(u);
}
__device__ __forceinline__ void cp16(uint32_t dst, const void* src) {
    asm volatile("cp.async.ca.shared.global [%0], [%1], 16;\n" :: "r"(dst), "l"(src));
}
#define MMA(acc, a, b0, b1)                                                    \
    asm volatile("mma.sync.aligned.m16n8k8.row.col.f32.tf32.tf32.f32 "         \
                 "{%0,%1,%2,%3}, {%4,%5,%6,%7}, {%8,%9}, {%0,%1,%2,%3};\n"     \
                 : "+f"(acc[0]), "+f"(acc[1]), "+f"(acc[2]), "+f"(acc[3])      \
                 : "r"(a.x), "r"(a.y), "r"(a.z), "r"(a.w), "r"(b0), "r"(b1))

// ------------------------------ pack X ----------------------------------
// g_Xp f4 idx: (((mt128*72 + chunk)*8 + mt16)*2 + ks)*32 + lane
// frag: e0=X(r,c) e1=X(r+8,c) e2=X(r,c+4) e3=X(r+8,c+4)
//   r = mt128*128 + mt16*16 + (lane>>2),  c = chunk*16 + ks*8 + (lane&3)
__global__ void __launch_bounds__(256) pack_x(const float* __restrict__ label,
                                              const float* __restrict__ chh) {
    const size_t i4 = (size_t)blockIdx.x * 256 + threadIdx.x;
    const int lane = (int)(i4 & 31);
    const int ks   = (int)((i4 >> 5) & 1);
    const int mt16 = (int)((i4 >> 6) & 7);
    const size_t blk = i4 >> 9;
    const int chunk = (int)(blk % NCH);
    const int mt128 = (int)(blk / NCH);

    const int r = mt128 * 128 + mt16 * 16 + (lane >> 2);
    const int c = chunk * 16 + ks * 8 + (lane & 3);

    const float* base; int stride, cc;
    if (c < 128)      { base = label;                    stride = 128; cc = c;       }
    else if (c < 640) { base = chh;                      stride = 512; cc = c - 128; }
    else              { base = chh + (size_t)BSZ * 512;  stride = 512; cc = c - 640; }

    float4 o;
    o.x = tfr(base[(size_t)r       * stride + cc]);
    o.y = tfr(base[(size_t)(r + 8) * stride + cc]);
    o.z = tfr(base[(size_t)r       * stride + cc + 4]);
    o.w = tfr(base[(size_t)(r + 8) * stride + cc + 4]);
    ((float4*)g_Xp)[i4] = o;
}

// ------------------------------ pack W ----------------------------------
__device__ __forceinline__ float wval(int n, int k,
    const float* Wi, const float* Wo, const float* Wu,
    const float* Wfl, const float* Wfs) {
    const int gate = n >> 9, h = n & 511;
    if (gate == 0) return Wi[(size_t)h * KD + k];
    if (gate == 1) return Wo[(size_t)h * KD + k];
    if (gate == 2) return Wu[(size_t)h * KD + k];
    const int kk = gate - 3;
    if (k < 128) return Wfl[(size_t)h * 128 + k];
    const int j = (k - 128) >> 9, kc = (k - 128) & 511;
    return Wfs[(((size_t)(kk * 2 + j)) * 512 + h) * 512 + kc];
}

// g_Wp f4 idx: (((nt*72 + chunk)*10 + pair)*2 + ks)*32 + lane
// packed col j (0..159) in tile nt: gate g=j/32, hl=j%32 -> orig n = g*512 + nt*32 + hl
__global__ void __launch_bounds__(256) pack_w(
    const float* __restrict__ Wi, const float* __restrict__ Wo,
    const float* __restrict__ Wu, const float* __restrict__ Wfl,
    const float* __restrict__ Wfs) {
    const size_t i4 = (size_t)blockIdx.x * 256 + threadIdx.x;   // < 16*72*640
    const int lane = (int)(i4 & 31);
    const int ks   = (int)((i4 >> 5) & 1);
    const int pair = (int)((i4 >> 6) % 10);
    const size_t blk = i4 / 640;
    const int chunk = (int)(blk % NCH);
    const int nt    = (int)(blk / NCH);

    const int j0 = pair * 16 + (lane >> 2);
    const int j1 = j0 + 8;
    const int n0 = (j0 >> 5) * 512 + nt * 32 + (j0 & 31);
    const int n1 = (j1 >> 5) * 512 + nt * 32 + (j1 & 31);
    const int k  = chunk * 16 + ks * 8 + (lane & 3);

    float4 o;
    o.x = tfr(wval(n0, k,     Wi, Wo, Wu, Wfl, Wfs));
    o.y = tfr(wval(n0, k + 4, Wi, Wo, Wu, Wfl, Wfs));
    o.z = tfr(wval(n1, k,     Wi, Wo, Wu, Wfl, Wfs));
    o.w = tfr(wval(n1, k + 4, Wi, Wo, Wu, Wfl, Wfs));
    ((float4*)g_Wp)[i4] = o;
}

// ---------------------- fused GEMM + epilogue ----------------------------
// CTA 256x160, 8 warps (4m x 2n), warp tile 64x80, mma m16n8k8 tf32.
// 4-stage cp.async pipeline (26KB/stage), 1 barrier per chunk, occ 1.
// A smem per stage: two 8KB pack-blocks (rows 0-127, 128-255).
__global__ void __launch_bounds__(256, 1) gemm_fused(
    const float* __restrict__ chc,
    const float* __restrict__ bi, const float* __restrict__ bo,
    const float* __restrict__ bu, const float* __restrict__ fb,
    float* __restrict__ out) {
    extern __shared__ float smf[];
    uint4* sm = (uint4*)smf;
    const uint32_t sb = (uint32_t)__cvta_generic_to_shared(smf);

    const int tid = threadIdx.x, warp = tid >> 5, lane = tid & 31;
    const int wm = warp >> 1, wn = warp & 1;     // 4 m-groups x 2 n-groups
    const int nt = blockIdx.x;                   // 0..15 (fast: weights L2-hot)
    const int mt = blockIdx.y;                   // 0..63

    const float4* gA = (const float4*)g_Xp + (size_t)(mt * 2) * NCH * 512;
    const float4* gB = (const float4*)g_Wp + (size_t)nt * NCH * 640;

    float acc[4][10][4];
    #pragma unroll
    for (int a = 0; a < 4; a++)
        #pragma unroll
        for (int b = 0; b < 10; b++)
            #pragma unroll
            for (int c = 0; c < 4; c++) acc[a][b][c] = 0.f;

    auto load = [&](int s, int c) {
        const uint32_t d = sb + s * (STAGE_F4 * 16);
        #pragma unroll
        for (int i = 0; i < 7; i++) {
            int idx = tid + i * 256;
            if (idx < 1024) {
                int blkb = idx >> 9, rest = idx & 511;
                cp16(d + idx * 16, gA + (size_t)blkb * NCH * 512 + (size_t)c * 512 + rest);
            } else if (idx < STAGE_F4) {
                cp16(d + idx * 16, gB + (size_t)c * 640 + (idx - 1024));
            }
        }
    };

    load(0, 0); asm volatile("cp.async.commit_group;");
    load(1, 1); asm volatile("cp.async.commit_group;");
    load(2, 2); asm volatile("cp.async.commit_group;");

    #pragma unroll 1
    for (int c = 0; c < NCH; c++) {
        if (c < NCH - 3) asm volatile("cp.async.wait_group 2;");
        else             asm volatile("cp.async.wait_group 0;");
        __syncthreads();
        if (c + 3 < NCH) {
            load((c + 3) & 3, c + 3);
            asm volatile("cp.async.commit_group;");
        }
        const uint4* S  = sm + (c & 3) * STAGE_F4;
        const uint4* Aw = S + (wm >> 1) * 512;          // pack block for this m-group
        const uint4* B4 = S + 1024;
        #pragma unroll
        for (int ks = 0; ks < 2; ks++) {
            uint4 a[4];
            #pragma unroll
            for (int mf = 0; mf < 4; mf++)
                a[mf] = Aw[(((wm & 1) * 4 + mf) * 2 + ks) * 32 + lane];
            #pragma unroll
            for (int q = 0; q < 5; q++) {
                uint4 b = B4[((wn * 5 + q) * 2 + ks) * 32 + lane];
                #pragma unroll
                for (int mf = 0; mf < 4; mf++) {
                    MMA(acc[mf][2 * q],     a[mf], b.x, b.y);
                    MMA(acc[mf][2 * q + 1], a[mf], b.z, b.w);
                }
            }
        }
    }

    // ---- epilogue: four 64-row quarters staged into dead mainloop smem ----
    const int hl = lane;
    const int h  = nt * 32 + hl;
    const float vbi = bi[h], vbo = bo[h], vbu = bu[h], vfb = fb[h];
    const size_t OUT2 = (size_t)BSZ * H;
    const int m0 = mt * 256;

    #pragma unroll 1
    for (int q = 0; q < 4; q++) {
        __syncthreads();          // buffer free (mainloop done / prev quarter done)
        if (wm == q) {            // warp rows = q*64 .. q*64+63 (local r = mf*16+(lane>>2))
            const int nb = wn * 80 + (lane & 3) * 2;
            #pragma unroll
            for (int mf = 0; mf < 4; mf++) {
                const int r = mf * 16 + (lane >> 2);
                #pragma unroll
                for (int nf = 0; nf < 10; nf++) {
                    const int n = nb + nf * 8;
                    smf[r * LDE + n]           = acc[mf][nf][0];
                    smf[r * LDE + n + 1]       = acc[mf][nf][1];
                    smf[(r + 8) * LDE + n]     = acc[mf][nf][2];
                    smf[(r + 8) * LDE + n + 1] = acc[mf][nf][3];
                }
            }
        }
        __syncthreads();
        #pragma unroll 1
        for (int e = 0; e < 8; e++) {
            const int ml = (tid >> 5) + e * 8;          // 0..63
            const float pi  = smf[ml * LDE + hl];
            const float po  = smf[ml * LDE + 32 + hl];
            const float pu  = smf[ml * LDE + 64 + hl];
            const float pf0 = smf[ml * LDE + 96 + hl];
            const float pf1 = smf[ml * LDE + 128 + hl];
            const size_t gi = (size_t)(m0 + q * 64 + ml) * H + h;
            const float c0 = chc[gi];
            const float c1 = chc[OUT2 + gi];
            const float ig = 1.f / (1.f + __expf(-(pi + vbi)));
            const float og = 1.f / (1.f + __expf(-(po + vbo)));
            const float uu = tanhf(pu + vbu);
            const float f0 = 1.f / (1.f + __expf(-pf0));
            const float f1 = 1.f / (1.f + __expf(-pf1));
            const float nc = ig * uu + f0 * c0 + f1 * c1 + vfb * (c0 + c1);
            out[gi] = nc;
            out[OUT2 + gi] = tanhf(og * nc);
        }
    }
}

// ------------------------------- launch ---------------------------------
extern "C" void kernel_launch(void* const* d_in, const int* in_sizes, int n_in,
                              void* d_out, int out_size) {
    const float* label = (const float*)d_in[0];
    const float* chh   = (const float*)d_in[1];
    const float* chc   = (const float*)d_in[2];
    const float* Wi    = (const float*)d_in[3];
    const float* bi    = (const float*)d_in[4];
    const float* Wo    = (const float*)d_in[5];
    const float* bo    = (const float*)d_in[6];
    const float* Wu    = (const float*)d_in[7];
    const float* bu    = (const float*)d_in[8];
    const float* Wfl   = (const float*)d_in[9];
    const float* Wfs   = (const float*)d_in[10];
    const float* fb    = (const float*)d_in[11];
    float* out = (float*)d_out;

    cudaFuncSetAttribute(gemm_fused, cudaFuncAttributeMaxDynamicSharedMemorySize, SMEM_DYN);

    pack_x<<<18432, 256>>>(label, chh);
    pack_w<<<2880, 256>>>(Wi, Wo, Wu, Wfl, Wfs);
    gemm_fused<<<dim3(NTILES, MTILES), 256, SMEM_DYN>>>(chc, bi, bo, bu, fb, out);
}

// round 16
// speedup vs baseline: 1.0437x; 1.0437x over previous
#include <cuda_runtime.h>
#include <cstdint>
#include <cstddef>

#define BSZ   16384
#define H     512
#define KD    1152            // 128 + 2*512
#define NTOT  2560            // 5 gates * 512
#define NCH   72              // K chunks of 16
#define NTILES 16             // 2560 / 160
#define MTILES 128            // 16384 / 128
#define LDE   165             // epilogue staging stride (floats)
#define STAGE_F4 1152         // A 512 f4 + B 640 f4 per chunk
#define SMEM_DYN 55296        // 3 * 18432; staging reuse = 64*165*4 = 42240

// --------- device-global scratch (no allocation calls anywhere) ----------
static __device__ float g_Xp[(size_t)BSZ * KD];          // 75.5 MB fragment-ordered
static __device__ float g_Wp[(size_t)NTOT * KD];         // 11.8 MB fragment-ordered

// ------------------------------ helpers ---------------------------------
__device__ __forceinline__ float tfr(float f) {
    uint32_t u; asm("cvt.rna.tf32.f32 %0, %1;" : "=r"(u) : "f"(f));
    return __uint_as_float(u);
}
__device__ __forceinline__ void cp16(uint32_t dst, const void* src) {
    asm volatile("cp.async.ca.shared.global [%0], [%1], 16;\n" :: "r"(dst), "l"(src));
}
#define MMA(acc, a, b0, b1)                                                    \
    asm volatile("mma.sync.aligned.m16n8k8.row.col.f32.tf32.tf32.f32 "         \
                 "{%0,%1,%2,%3}, {%4,%5,%6,%7}, {%8,%9}, {%0,%1,%2,%3};\n"     \
                 : "+f"(acc[0]), "+f"(acc[1]), "+f"(acc[2]), "+f"(acc[3])      \
                 : "r"(a.x), "r"(a.y), "r"(a.z), "r"(a.w), "r"(b0), "r"(b1))

// ------------------------------ pack X ----------------------------------
// g_Xp f4 idx: (((mt128*72 + chunk)*8 + mt16)*2 + ks)*32 + lane
// frag: e0=X(r,c) e1=X(r+8,c) e2=X(r,c+4) e3=X(r+8,c+4)
//   r = mt128*128 + mt16*16 + (lane>>2),  c = chunk*16 + ks*8 + (lane&3)
__global__ void __launch_bounds__(256) pack_x(const float* __restrict__ label,
                                              const float* __restrict__ chh) {
    const size_t i4 = (size_t)blockIdx.x * 256 + threadIdx.x;
    const int lane = (int)(i4 & 31);
    const int ks   = (int)((i4 >> 5) & 1);
    const int mt16 = (int)((i4 >> 6) & 7);
    const size_t blk = i4 >> 9;
    const int chunk = (int)(blk % NCH);
    const int mt128 = (int)(blk / NCH);

    const int r = mt128 * 128 + mt16 * 16 + (lane >> 2);
    const int c = chunk * 16 + ks * 8 + (lane & 3);

    const float* base; int stride, cc;
    if (c < 128)      { base = label;                    stride = 128; cc = c;       }
    else if (c < 640) { base = chh;                      stride = 512; cc = c - 128; }
    else              { base = chh + (size_t)BSZ * 512;  stride = 512; cc = c - 640; }

    float4 o;
    o.x = tfr(base[(size_t)r       * stride + cc]);
    o.y = tfr(base[(size_t)(r + 8) * stride + cc]);
    o.z = tfr(base[(size_t)r       * stride + cc + 4]);
    o.w = tfr(base[(size_t)(r + 8) * stride + cc + 4]);
    ((float4*)g_Xp)[i4] = o;
}

// ------------------------------ pack W ----------------------------------
__device__ __forceinline__ float wval(int n, int k,
    const float* Wi, const float* Wo, const float* Wu,
    const float* Wfl, const float* Wfs) {
    const int gate = n >> 9, h = n & 511;
    if (gate == 0) return Wi[(size_t)h * KD + k];
    if (gate == 1) return Wo[(size_t)h * KD + k];
    if (gate == 2) return Wu[(size_t)h * KD + k];
    const int kk = gate - 3;
    if (k < 128) return Wfl[(size_t)h * 128 + k];
    const int j = (k - 128) >> 9, kc = (k - 128) & 511;
    return Wfs[(((size_t)(kk * 2 + j)) * 512 + h) * 512 + kc];
}

// g_Wp f4 idx: (((nt*72 + chunk)*10 + pair)*2 + ks)*32 + lane
// packed col j (0..159) in tile nt: gate g=j/32, hl=j%32 -> orig n = g*512 + nt*32 + hl
__global__ void __launch_bounds__(256) pack_w(
    const float* __restrict__ Wi, const float* __restrict__ Wo,
    const float* __restrict__ Wu, const float* __restrict__ Wfl,
    const float* __restrict__ Wfs) {
    const size_t i4 = (size_t)blockIdx.x * 256 + threadIdx.x;   // < 16*72*640
    const int lane = (int)(i4 & 31);
    const int ks   = (int)((i4 >> 5) & 1);
    const int pair = (int)((i4 >> 6) % 10);
    const size_t blk = i4 / 640;
    const int chunk = (int)(blk % NCH);
    const int nt    = (int)(blk / NCH);

    const int j0 = pair * 16 + (lane >> 2);
    const int j1 = j0 + 8;
    const int n0 = (j0 >> 5) * 512 + nt * 32 + (j0 & 31);
    const int n1 = (j1 >> 5) * 512 + nt * 32 + (j1 & 31);
    const int k  = chunk * 16 + ks * 8 + (lane & 3);

    float4 o;
    o.x = tfr(wval(n0, k,     Wi, Wo, Wu, Wfl, Wfs));
    o.y = tfr(wval(n0, k + 4, Wi, Wo, Wu, Wfl, Wfs));
    o.z = tfr(wval(n1, k,     Wi, Wo, Wu, Wfl, Wfs));
    o.w = tfr(wval(n1, k + 4, Wi, Wo, Wu, Wfl, Wfs));
    ((float4*)g_Wp)[i4] = o;
}

// ---------------------- fused GEMM + epilogue ----------------------------
// CTA 128x160, 4 warps (2m x 2n), warp tile 64x80, mma m16n8k8 tf32, occ 2.
// 3-stage cp.async pipeline (18KB/stage), single barrier per chunk.
// Epilogue: two 64-row halves staged into the (dead) mainloop smem.
__global__ void __launch_bounds__(128, 2) gemm_fused(
    const float* __restrict__ chc,
    const float* __restrict__ bi, const float* __restrict__ bo,
    const float* __restrict__ bu, const float* __restrict__ fb,
    float* __restrict__ out) {
    extern __shared__ float smf[];
    uint4* sm = (uint4*)smf;
    const uint32_t sb = (uint32_t)__cvta_generic_to_shared(smf);

    const int tid = threadIdx.x, warp = tid >> 5, lane = tid & 31;
    const int wm = warp >> 1, wn = warp & 1;   // 2 m-groups x 2 n-groups
    const int nt = blockIdx.x;                 // 0..15 (fast: weights L2-hot)
    const int mt = blockIdx.y;                 // 0..127

    const float4* gA = (const float4*)g_Xp + (size_t)mt * NCH * 512;
    const float4* gB = (const float4*)g_Wp + (size_t)nt * NCH * 640;

    float acc[4][10][4];
    #pragma unroll
    for (int a = 0; a < 4; a++)
        #pragma unroll
        for (int b = 0; b < 10; b++)
            #pragma unroll
            for (int c = 0; c < 4; c++) acc[a][b][c] = 0.f;

    auto load = [&](int s, int c) {
        const float4* a = gA + (size_t)c * 512;
        const float4* b = gB + (size_t)c * 640;
        const uint32_t d = sb + s * (STAGE_F4 * 16);
        #pragma unroll
        for (int i = 0; i < 9; i++) {
            int idx = tid + i * 128;
            if (idx < 512)           cp16(d + idx * 16, a + idx);
            else                     cp16(d + idx * 16, b + (idx - 512));
        }
    };

    load(0, 0); asm volatile("cp.async.commit_group;");
    load(1, 1); asm volatile("cp.async.commit_group;");

    #pragma unroll 1
    for (int c = 0; c < NCH; c++) {
        if (c < NCH - 2) asm volatile("cp.async.wait_group 1;");
        else             asm volatile("cp.async.wait_group 0;");
        __syncthreads();
        if (c + 2 < NCH) {
            load((c + 2) % 3, c + 2);
            asm volatile("cp.async.commit_group;");
        }
        const uint4* A4 = sm + (c % 3) * STAGE_F4;
        const uint4* B4 = A4 + 512;
        #pragma unroll
        for (int ks = 0; ks < 2; ks++) {
            uint4 a[4];
            #pragma unroll
            for (int mf = 0; mf < 4; mf++)
                a[mf] = A4[((wm * 4 + mf) * 2 + ks) * 32 + lane];
            #pragma unroll
            for (int q = 0; q < 5; q++) {
                uint4 b = B4[((wn * 5 + q) * 2 + ks) * 32 + lane];
                #pragma unroll
                for (int mf = 0; mf < 4; mf++) {
                    MMA(acc[mf][2 * q],     a[mf], b.x, b.y);
                    MMA(acc[mf][2 * q + 1], a[mf], b.z, b.w);
                }
            }
        }
    }

    // ---- epilogue in two 64-row halves, reusing mainloop smem ----
    const int hl = lane;
    const int h  = nt * 32 + hl;
    const float vbi = bi[h], vbo = bo[h], vbu = bu[h], vfb = fb[h];
    const size_t OUT2 = (size_t)BSZ * H;
    const int m0 = mt * 128;

    #pragma unroll 1
    for (int half = 0; half < 2; half++) {
        __syncthreads();        // staging buffer free (mainloop done / prev half done)
        if (wm == half) {       // this warp's 64 rows are this half
            const int nb = wn * 80 + (lane & 3) * 2;
            #pragma unroll
            for (int mf = 0; mf < 4; mf++) {
                const int r = mf * 16 + (lane >> 2);
                #pragma unroll
                for (int nf = 0; nf < 10; nf++) {
                    const int n = nb + nf * 8;
                    smf[r * LDE + n]           = acc[mf][nf][0];
                    smf[r * LDE + n + 1]       = acc[mf][nf][1];
                    smf[(r + 8) * LDE + n]     = acc[mf][nf][2];
                    smf[(r + 8) * LDE + n + 1] = acc[mf][nf][3];
                }
            }
        }
        __syncthreads();
        #pragma unroll 1
        for (int e = 0; e < 16; e++) {
            const int ml = (tid >> 5) + e * 4;          // 0..63
            const float pi  = smf[ml * LDE + hl];
            const float po  = smf[ml * LDE + 32 + hl];
            const float pu  = smf[ml * LDE + 64 + hl];
            const float pf0 = smf[ml * LDE + 96 + hl];
            const float pf1 = smf[ml * LDE + 128 + hl];
            const size_t gi = (size_t)(m0 + half * 64 + ml) * H + h;
            const float c0 = chc[gi];
            const float c1 = chc[OUT2 + gi];
            const float ig = 1.f / (1.f + __expf(-(pi + vbi)));
            const float og = 1.f / (1.f + __expf(-(po + vbo)));
            const float uu = tanhf(pu + vbu);
            const float f0 = 1.f / (1.f + __expf(-pf0));
            const float f1 = 1.f / (1.f + __expf(-pf1));
            const float nc = ig * uu + f0 * c0 + f1 * c1 + vfb * (c0 + c1);
            out[gi] = nc;
            out[OUT2 + gi] = tanhf(og * nc);
        }
    }
}

// ------------------------------- launch ---------------------------------
extern "C" void kernel_launch(void* const* d_in, const int* in_sizes, int n_in,
                              void* d_out, int out_size) {
    const float* label = (const float*)d_in[0];
    const float* chh   = (const float*)d_in[1];
    const float* chc   = (const float*)d_in[2];
    const float* Wi    = (const float*)d_in[3];
    const float* bi    = (const float*)d_in[4];
    const float* Wo    = (const float*)d_in[5];
    const float* bo    = (const float*)d_in[6];
    const float* Wu    = (const float*)d_in[7];
    const float* bu    = (const float*)d_in[8];
    const float* Wfl   = (const float*)d_in[9];
    const float* Wfs   = (const float*)d_in[10];
    const float* fb    = (const float*)d_in[11];
    float* out = (float*)d_out;

    cudaFuncSetAttribute(gemm_fused, cudaFuncAttributeMaxDynamicSharedMemorySize, SMEM_DYN);

    pack_x<<<18432, 256>>>(label, chh);
    pack_w<<<2880, 256>>>(Wi, Wo, Wu, Wfl, Wfs);
    gemm_fused<<<dim3(NTILES, MTILES), 128, SMEM_DYN>>>(chc, bi, bo, bu, fb, out);
}

// round 17
// speedup vs baseline: 1.2071x; 1.1565x over previous
#include <cuda_runtime.h>
#include <cstdint>
#include <cstddef>

#define BSZ   16384
#define H     512
#define KD    1152            // 128 + 2*512
#define NCH16 72              // K chunks of 16 (pack granularity)
#define NCHU  36              // K chunks of 32 (mainloop granularity)
#define NTILES 16             // 2560 / 160
#define MTILES 128            // 16384 / 128
#define LDE   165             // epilogue staging stride (floats)
#define STAGE_F4 2304         // A 1024 f4 + B 1280 f4 per k32 chunk
#define SMEM_DYN (2 * STAGE_F4 * 16)   // 73728; staging reuse = 64*165*4 = 42240

// --------- device-global scratch (no allocation calls anywhere) ----------
static __device__ float g_Xp[(size_t)BSZ * KD];          // 75.5 MB fragment-ordered
static __device__ float g_Wp[(size_t)2560 * KD];         // 11.8 MB fragment-ordered

// ------------------------------ helpers ---------------------------------
__device__ __forceinline__ float tfr(float f) {
    uint32_t u; asm("cvt.rna.tf32.f32 %0, %1;" : "=r"(u) : "f"(f));
    return __uint_as_float(u);
}
__device__ __forceinline__ void cp16(uint32_t dst, const void* src) {
    asm volatile("cp.async.ca.shared.global [%0], [%1], 16;\n" :: "r"(dst), "l"(src));
}
#define MMA(acc, a, b0, b1)                                                    \
    asm volatile("mma.sync.aligned.m16n8k8.row.col.f32.tf32.tf32.f32 "         \
                 "{%0,%1,%2,%3}, {%4,%5,%6,%7}, {%8,%9}, {%0,%1,%2,%3};\n"     \
                 : "+f"(acc[0]), "+f"(acc[1]), "+f"(acc[2]), "+f"(acc[3])      \
                 : "r"(a.x), "r"(a.y), "r"(a.z), "r"(a.w), "r"(b0), "r"(b1))

// ------------------------------ pack X ----------------------------------
// g_Xp f4 idx: (((mt128*72 + chunk)*8 + mt16)*2 + ks)*32 + lane
// frag: e0=X(r,c) e1=X(r+8,c) e2=X(r,c+4) e3=X(r+8,c+4)
//   r = mt128*128 + mt16*16 + (lane>>2),  c = chunk*16 + ks*8 + (lane&3)
__global__ void __launch_bounds__(256) pack_x(const float* __restrict__ label,
                                              const float* __restrict__ chh) {
    const size_t i4 = (size_t)blockIdx.x * 256 + threadIdx.x;
    const int lane = (int)(i4 & 31);
    const int ks   = (int)((i4 >> 5) & 1);
    const int mt16 = (int)((i4 >> 6) & 7);
    const size_t blk = i4 >> 9;
    const int chunk = (int)(blk % NCH16);
    const int mt128 = (int)(blk / NCH16);

    const int r = mt128 * 128 + mt16 * 16 + (lane >> 2);
    const int c = chunk * 16 + ks * 8 + (lane & 3);

    const float* base; int stride, cc;
    if (c < 128)      { base = label;                    stride = 128; cc = c;       }
    else if (c < 640) { base = chh;                      stride = 512; cc = c - 128; }
    else              { base = chh + (size_t)BSZ * 512;  stride = 512; cc = c - 640; }

    float4 o;
    o.x = tfr(base[(size_t)r       * stride + cc]);
    o.y = tfr(base[(size_t)(r + 8) * stride + cc]);
    o.z = tfr(base[(size_t)r       * stride + cc + 4]);
    o.w = tfr(base[(size_t)(r + 8) * stride + cc + 4]);
    ((float4*)g_Xp)[i4] = o;
}

// ------------------------------ pack W ----------------------------------
__device__ __forceinline__ float wval(int n, int k,
    const float* Wi, const float* Wo, const float* Wu,
    const float* Wfl, const float* Wfs) {
    const int gate = n >> 9, h = n & 511;
    if (gate == 0) return Wi[(size_t)h * KD + k];
    if (gate == 1) return Wo[(size_t)h * KD + k];
    if (gate == 2) return Wu[(size_t)h * KD + k];
    const int kk = gate - 3;
    if (k < 128) return Wfl[(size_t)h * 128 + k];
    const int j = (k - 128) >> 9, kc = (k - 128) & 511;
    return Wfs[(((size_t)(kk * 2 + j)) * 512 + h) * 512 + kc];
}

// g_Wp f4 idx: (((nt*72 + chunk)*10 + pair)*2 + ks)*32 + lane
// packed col j (0..159) in tile nt: gate g=j/32, hl=j%32 -> orig n = g*512 + nt*32 + hl
__global__ void __launch_bounds__(256) pack_w(
    const float* __restrict__ Wi, const float* __restrict__ Wo,
    const float* __restrict__ Wu, const float* __restrict__ Wfl,
    const float* __restrict__ Wfs) {
    const size_t i4 = (size_t)blockIdx.x * 256 + threadIdx.x;   // < 16*72*640
    const int lane = (int)(i4 & 31);
    const int ks   = (int)((i4 >> 5) & 1);
    const int pair = (int)((i4 >> 6) % 10);
    const size_t blk = i4 / 640;
    const int chunk = (int)(blk % NCH16);
    const int nt    = (int)(blk / NCH16);

    const int j0 = pair * 16 + (lane >> 2);
    const int j1 = j0 + 8;
    const int n0 = (j0 >> 5) * 512 + nt * 32 + (j0 & 31);
    const int n1 = (j1 >> 5) * 512 + nt * 32 + (j1 & 31);
    const int k  = chunk * 16 + ks * 8 + (lane & 3);

    float4 o;
    o.x = tfr(wval(n0, k,     Wi, Wo, Wu, Wfl, Wfs));
    o.y = tfr(wval(n0, k + 4, Wi, Wo, Wu, Wfl, Wfs));
    o.z = tfr(wval(n1, k,     Wi, Wo, Wu, Wfl, Wfs));
    o.w = tfr(wval(n1, k + 4, Wi, Wo, Wu, Wfl, Wfs));
    ((float4*)g_Wp)[i4] = o;
}

// ---------------------- fused GEMM + epilogue ----------------------------
// CTA 128x160, 8 warps (4m x 2n), warp tile 32x80, mma m16n8k8 tf32, occ 2.
// k32 chunks, 2-stage cp.async pipeline (36KB/stage), 1 barrier per chunk.
// Load issued after the barrier => race-free single-barrier 2-stage scheme.
__global__ void __launch_bounds__(256, 2) gemm_fused(
    const float* __restrict__ chc,
    const float* __restrict__ bi, const float* __restrict__ bo,
    const float* __restrict__ bu, const float* __restrict__ fb,
    float* __restrict__ out) {
    extern __shared__ float smf[];
    uint4* sm = (uint4*)smf;
    const uint32_t sb = (uint32_t)__cvta_generic_to_shared(smf);

    const int tid = threadIdx.x, warp = tid >> 5, lane = tid & 31;
    const int wm2 = (warp >> 1) * 2;      // A subtile16 base
    const int wn5 = (warp & 1) * 5;       // B pair base
    const int nt = blockIdx.x;            // 0..15 (fast: weights L2-hot)
    const int mt = blockIdx.y;            // 0..127

    // k32 chunk c covers pack chunks 2c,2c+1 -> contiguous 1024/1280 f4 blocks
    const float4* gA = (const float4*)g_Xp + (size_t)mt * NCH16 * 512;
    const float4* gB = (const float4*)g_Wp + (size_t)nt * NCH16 * 640;

    float acc[2][10][4];
    #pragma unroll
    for (int a = 0; a < 2; a++)
        #pragma unroll
        for (int b = 0; b < 10; b++)
            #pragma unroll
            for (int c = 0; c < 4; c++) acc[a][b][c] = 0.f;

    auto load = [&](int s, int c) {
        const float4* a = gA + (size_t)c * 1024;
        const float4* b = gB + (size_t)c * 1280;
        const uint32_t d = sb + s * (STAGE_F4 * 16);
        #pragma unroll
        for (int i = 0; i < 9; i++) {
            int idx = tid + i * 256;
            if (idx < 1024)           cp16(d + idx * 16, a + idx);
            else                      cp16(d + idx * 16, b + (idx - 1024));
        }
    };

    load(0, 0); asm volatile("cp.async.commit_group;");

    #pragma unroll 1
    for (int c = 0; c < NCHU; c++) {
        asm volatile("cp.async.wait_group 0;");
        __syncthreads();
        if (c + 1 < NCHU) {
            load((c + 1) & 1, c + 1);
            asm volatile("cp.async.commit_group;");
        }
        const uint4* S = sm + (c & 1) * STAGE_F4;
        #pragma unroll
        for (int half = 0; half < 2; half++) {          // pack chunk 2c / 2c+1
            const uint4* A4 = S + half * 512;
            const uint4* B4 = S + 1024 + half * 640;
            #pragma unroll
            for (int ks = 0; ks < 2; ks++) {
                uint4 a0 = A4[((wm2 + 0) * 2 + ks) * 32 + lane];
                uint4 a1 = A4[((wm2 + 1) * 2 + ks) * 32 + lane];
                #pragma unroll
                for (int q = 0; q < 5; q++) {
                    uint4 b = B4[((wn5 + q) * 2 + ks) * 32 + lane];
                    MMA(acc[0][2 * q],     a0, b.x, b.y);
                    MMA(acc[0][2 * q + 1], a0, b.z, b.w);
                    MMA(acc[1][2 * q],     a1, b.x, b.y);
                    MMA(acc[1][2 * q + 1], a1, b.z, b.w);
                }
            }
        }
    }

    // ---- epilogue in two 64-row halves, reusing mainloop smem ----
    const int hl = lane;
    const int h  = nt * 32 + hl;
    const float vbi = bi[h], vbo = bo[h], vbu = bu[h], vfb = fb[h];
    const size_t OUT2 = (size_t)BSZ * H;
    const int m0 = mt * 128;

    #pragma unroll 1
    for (int half = 0; half < 2; half++) {
        __syncthreads();        // staging buffer free (mainloop done / prev half done)
        if ((warp >> 2) == half) {
            const int r0 = ((warp >> 1) & 1) * 32 + (lane >> 2);  // local row base
            const int nb = (warp & 1) * 80 + (lane & 3) * 2;
            #pragma unroll
            for (int mf = 0; mf < 2; mf++) {
                const int r = r0 + mf * 16;
                #pragma unroll
                for (int nf = 0; nf < 10; nf++) {
                    const int n = nb + nf * 8;
                    smf[r * LDE + n]           = acc[mf][nf][0];
                    smf[r * LDE + n + 1]       = acc[mf][nf][1];
                    smf[(r + 8) * LDE + n]     = acc[mf][nf][2];
                    smf[(r + 8) * LDE + n + 1] = acc[mf][nf][3];
                }
            }
        }
        __syncthreads();
        #pragma unroll 1
        for (int e = 0; e < 8; e++) {
            const int ml = (tid >> 5) + e * 8;          // 0..63
            const float pi  = smf[ml * LDE + hl];
            const float po  = smf[ml * LDE + 32 + hl];
            const float pu  = smf[ml * LDE + 64 + hl];
            const float pf0 = smf[ml * LDE + 96 + hl];
            const float pf1 = smf[ml * LDE + 128 + hl];
            const size_t gi = (size_t)(m0 + half * 64 + ml) * H + h;
            const float c0 = chc[gi];
            const float c1 = chc[OUT2 + gi];
            const float ig = 1.f / (1.f + __expf(-(pi + vbi)));
            const float og = 1.f / (1.f + __expf(-(po + vbo)));
            const float uu = tanhf(pu + vbu);
            const float f0 = 1.f / (1.f + __expf(-pf0));
            const float f1 = 1.f / (1.f + __expf(-pf1));
            const float nc = ig * uu + f0 * c0 + f1 * c1 + vfb * (c0 + c1);
            out[gi] = nc;
            out[OUT2 + gi] = tanhf(og * nc);
        }
    }
}

// ------------------------------- launch ---------------------------------
extern "C" void kernel_launch(void* const* d_in, const int* in_sizes, int n_in,
                              void* d_out, int out_size) {
    const float* label = (const float*)d_in[0];
    const float* chh   = (const float*)d_in[1];
    const float* chc   = (const float*)d_in[2];
    const float* Wi    = (const float*)d_in[3];
    const float* bi    = (const float*)d_in[4];
    const float* Wo    = (const float*)d_in[5];
    const float* bo    = (const float*)d_in[6];
    const float* Wu    = (const float*)d_in[7];
    const float* bu    = (const float*)d_in[8];
    const float* Wfl   = (const float*)d_in[9];
    const float* Wfs   = (const float*)d_in[10];
    const float* fb    = (const float*)d_in[11];
    float* out = (float*)d_out;

    cudaFuncSetAttribute(gemm_fused, cudaFuncAttributeMaxDynamicSharedMemorySize, SMEM_DYN);

    pack_x<<<18432, 256>>>(label, chh);
    pack_w<<<2880, 256>>>(Wi, Wo, Wu, Wfl, Wfs);
    gemm_fused<<<dim3(NTILES, MTILES), 256, SMEM_DYN>>>(chc, bi, bo, bu, fb, out);
}